// round 2
// baseline (speedup 1.0000x reference)
#include <cuda_runtime.h>
#include <cuda_bf16.h>
#include <math.h>

// Problem constants
#define BB 128
#define SS 1024
#define IND 256
#define DD 128
#define MM 64
#define OUTD 128
#define NROWS (BB * SS)   // 131072

// Scratch (device globals; no runtime allocation allowed)
// g_pack per (b,s): [0..64) w, [64..192) e, [192..320) a
__device__ float g_pack[(size_t)NROWS * 320];
__device__ float g_r[(size_t)NROWS * DD];
__device__ float g_wf[IND * MM];   // Wr @ MK^T  [256,64]
__device__ float g_bf[MM];         // br @ MK^T  [64]

// ---------------- f32x2 helpers (sm_100+ packed fp32) ----------------
__device__ __forceinline__ unsigned long long f2fma(unsigned long long a,
                                                    unsigned long long b,
                                                    unsigned long long c) {
    unsigned long long d;
    asm("fma.rn.f32x2 %0, %1, %2, %3;" : "=l"(d) : "l"(a), "l"(b), "l"(c));
    return d;
}
__device__ __forceinline__ unsigned long long f2add(unsigned long long a,
                                                    unsigned long long b) {
    unsigned long long d;
    asm("add.rn.f32x2 %0, %1, %2;" : "=l"(d) : "l"(a), "l"(b));
    return d;
}

// ---------------- fast activations (MUFU based) ----------------
__device__ __forceinline__ float fast_sigmoid(float v) {
    float t = __expf(-v);
    return __fdividef(1.0f, 1.0f + t);
}
__device__ __forceinline__ float fast_tanh(float v) {
    float t = __expf(fminf(2.0f * v, 80.0f));
    return __fdividef(t - 1.0f, t + 1.0f);
}

// =====================================================================
// Kernel 0: prep.  g_wf = Wr @ MK^T, g_bf = br @ MK^T.   (tiny)
// =====================================================================
__global__ __launch_bounds__(256) void prep_kernel(const float* __restrict__ Wr,
                                                   const float* __restrict__ br,
                                                   const float* __restrict__ mk) {
    int gid = blockIdx.x * 256 + threadIdx.x;   // 0..16383
    int i = gid >> 6, m = gid & 63;
    float s = 0.f;
    const float* wr = Wr + i * 128;
    const float* mr = mk + m * 128;
#pragma unroll 4
    for (int d = 0; d < 128; d += 4) {
        float4 a = *(const float4*)(wr + d);
        float4 b = *(const float4*)(mr + d);
        s += a.x * b.x + a.y * b.y + a.z * b.z + a.w * b.w;
    }
    g_wf[i * 64 + m] = s;
    if (gid < 64) {
        float sb = 0.f;
        const float* mr2 = mk + gid * 128;
        for (int d = 0; d < 128; d++) sb += br[d] * mr2[d];
        g_bf[gid] = sb;
    }
}

// =====================================================================
// Kernel 1: v-projection.  v = x@Ww + bw -> e=sigmoid(v), a=tanh(v) -> g_pack
// 128x128 tile, K=256, BK=16, 8x8/thread, register-prefetch pipeline.
// =====================================================================
__global__ __launch_bounds__(256, 2) void vproj_kernel(
    const float* __restrict__ x,
    const float* __restrict__ Ww, const float* __restrict__ bw) {
    __shared__ __align__(16) float As[16][132];
    __shared__ __align__(16) float Bs[16][128];

    const int row0 = blockIdx.x * 128;
    const int t = threadIdx.x;
    const int tm = (t >> 4) * 8;
    const int tn = (t & 15) * 8;

    // load-index precompute
    const int mA0 = t >> 2;                // 0..63
    const int kqA = (t & 3) * 4;           // 0,4,8,12
    const int kkB0 = t >> 5;               // 0..7
    const int nqB = (t & 31) * 4;

    const float* xA0 = x + (size_t)(row0 + mA0) * IND + kqA;
    const float* xA1 = x + (size_t)(row0 + mA0 + 64) * IND + kqA;
    const float* wB0 = Ww + (size_t)kkB0 * 128 + nqB;
    const float* wB1 = Ww + (size_t)(kkB0 + 8) * 128 + nqB;

    float acc[8][8];
#pragma unroll
    for (int i = 0; i < 8; i++)
#pragma unroll
        for (int j = 0; j < 8; j++) acc[i][j] = 0.f;

    float4 rA0, rA1, rB0, rB1;
    // prologue load k0=0
    rA0 = *(const float4*)(xA0);
    rA1 = *(const float4*)(xA1);
    rB0 = *(const float4*)(wB0);
    rB1 = *(const float4*)(wB1);
    As[kqA + 0][mA0] = rA0.x; As[kqA + 1][mA0] = rA0.y;
    As[kqA + 2][mA0] = rA0.z; As[kqA + 3][mA0] = rA0.w;
    As[kqA + 0][mA0 + 64] = rA1.x; As[kqA + 1][mA0 + 64] = rA1.y;
    As[kqA + 2][mA0 + 64] = rA1.z; As[kqA + 3][mA0 + 64] = rA1.w;
    *(float4*)&Bs[kkB0][nqB] = rB0;
    *(float4*)&Bs[kkB0 + 8][nqB] = rB1;
    __syncthreads();

    for (int k0 = 16; k0 < IND; k0 += 16) {
        // prefetch next chunk into registers
        rA0 = *(const float4*)(xA0 + k0);
        rA1 = *(const float4*)(xA1 + k0);
        rB0 = *(const float4*)(wB0 + (size_t)k0 * 128);
        rB1 = *(const float4*)(wB1 + (size_t)k0 * 128);
        // compute current chunk
#pragma unroll
        for (int kk = 0; kk < 16; kk++) {
            float a[8], b[8];
            *(float4*)(a)     = *(const float4*)&As[kk][tm];
            *(float4*)(a + 4) = *(const float4*)&As[kk][tm + 4];
            *(float4*)(b)     = *(const float4*)&Bs[kk][tn];
            *(float4*)(b + 4) = *(const float4*)&Bs[kk][tn + 4];
#pragma unroll
            for (int i = 0; i < 8; i++)
#pragma unroll
                for (int j = 0; j < 8; j++) acc[i][j] = fmaf(a[i], b[j], acc[i][j]);
        }
        __syncthreads();
        As[kqA + 0][mA0] = rA0.x; As[kqA + 1][mA0] = rA0.y;
        As[kqA + 2][mA0] = rA0.z; As[kqA + 3][mA0] = rA0.w;
        As[kqA + 0][mA0 + 64] = rA1.x; As[kqA + 1][mA0 + 64] = rA1.y;
        As[kqA + 2][mA0 + 64] = rA1.z; As[kqA + 3][mA0 + 64] = rA1.w;
        *(float4*)&Bs[kkB0][nqB] = rB0;
        *(float4*)&Bs[kkB0 + 8][nqB] = rB1;
        __syncthreads();
    }
    // last chunk compute
#pragma unroll
    for (int kk = 0; kk < 16; kk++) {
        float a[8], b[8];
        *(float4*)(a)     = *(const float4*)&As[kk][tm];
        *(float4*)(a + 4) = *(const float4*)&As[kk][tm + 4];
        *(float4*)(b)     = *(const float4*)&Bs[kk][tn];
        *(float4*)(b + 4) = *(const float4*)&Bs[kk][tn + 4];
#pragma unroll
        for (int i = 0; i < 8; i++)
#pragma unroll
            for (int j = 0; j < 8; j++) acc[i][j] = fmaf(a[i], b[j], acc[i][j]);
    }

    float bb[8];
    *(float4*)(bb)     = *(const float4*)(bw + tn);
    *(float4*)(bb + 4) = *(const float4*)(bw + tn + 4);

#pragma unroll
    for (int i = 0; i < 8; i++) {
        size_t row = (size_t)(row0 + tm + i);
        float e[8], av[8];
#pragma unroll
        for (int j = 0; j < 8; j++) {
            float v = acc[i][j] + bb[j];
            e[j]  = fast_sigmoid(v);
            av[j] = fast_tanh(v);
        }
        float* pr = g_pack + row * 320;
        *(float4*)(pr + 64 + tn)      = *(float4*)(e);
        *(float4*)(pr + 64 + tn + 4)  = *(float4*)(e + 4);
        *(float4*)(pr + 192 + tn)     = *(float4*)(av);
        *(float4*)(pr + 192 + tn + 4) = *(float4*)(av + 4);
    }
}

// =====================================================================
// Kernel 2: w-projection + softmax.  w = softmax(x@Wf + bf) -> g_pack[.,0..64)
// 256x64 tile, K=256, BK=16, 8x8/thread (8 threads per row-group in n).
// =====================================================================
__global__ __launch_bounds__(256, 2) void wproj_kernel(const float* __restrict__ x) {
    __shared__ __align__(16) float As[16][260];
    __shared__ __align__(16) float Bs[16][64];

    const int row0 = blockIdx.x * 256;
    const int t = threadIdx.x;
    const int tm = (t >> 3) * 8;          // 0..248
    const int tn = (t & 7) * 8;           // 0..56

    const int mA0 = t >> 2;               // 0..63
    const int kqA = (t & 3) * 4;
    const int kkB = t >> 4;               // 0..15
    const int nqB = (t & 15) * 4;

    const float* xA = x + (size_t)(row0 + mA0) * IND + kqA;
    const float* wB = g_wf + (size_t)kkB * 64 + nqB;

    float acc[8][8];
#pragma unroll
    for (int i = 0; i < 8; i++)
#pragma unroll
        for (int j = 0; j < 8; j++) acc[i][j] = 0.f;

    float4 rA[4];
    float4 rB;
    // prologue k0=0
#pragma unroll
    for (int u = 0; u < 4; u++) rA[u] = *(const float4*)(xA + (size_t)(u * 64) * IND);
    rB = *(const float4*)(wB);
#pragma unroll
    for (int u = 0; u < 4; u++) {
        As[kqA + 0][mA0 + u * 64] = rA[u].x; As[kqA + 1][mA0 + u * 64] = rA[u].y;
        As[kqA + 2][mA0 + u * 64] = rA[u].z; As[kqA + 3][mA0 + u * 64] = rA[u].w;
    }
    *(float4*)&Bs[kkB][nqB] = rB;
    __syncthreads();

    for (int k0 = 16; k0 < IND; k0 += 16) {
#pragma unroll
        for (int u = 0; u < 4; u++) rA[u] = *(const float4*)(xA + (size_t)(u * 64) * IND + k0);
        rB = *(const float4*)(wB + (size_t)k0 * 64);
#pragma unroll
        for (int kk = 0; kk < 16; kk++) {
            float a[8], b[8];
            *(float4*)(a)     = *(const float4*)&As[kk][tm];
            *(float4*)(a + 4) = *(const float4*)&As[kk][tm + 4];
            *(float4*)(b)     = *(const float4*)&Bs[kk][tn];
            *(float4*)(b + 4) = *(const float4*)&Bs[kk][tn + 4];
#pragma unroll
            for (int i = 0; i < 8; i++)
#pragma unroll
                for (int j = 0; j < 8; j++) acc[i][j] = fmaf(a[i], b[j], acc[i][j]);
        }
        __syncthreads();
#pragma unroll
        for (int u = 0; u < 4; u++) {
            As[kqA + 0][mA0 + u * 64] = rA[u].x; As[kqA + 1][mA0 + u * 64] = rA[u].y;
            As[kqA + 2][mA0 + u * 64] = rA[u].z; As[kqA + 3][mA0 + u * 64] = rA[u].w;
        }
        *(float4*)&Bs[kkB][nqB] = rB;
        __syncthreads();
    }
#pragma unroll
    for (int kk = 0; kk < 16; kk++) {
        float a[8], b[8];
        *(float4*)(a)     = *(const float4*)&As[kk][tm];
        *(float4*)(a + 4) = *(const float4*)&As[kk][tm + 4];
        *(float4*)(b)     = *(const float4*)&Bs[kk][tn];
        *(float4*)(b + 4) = *(const float4*)&Bs[kk][tn + 4];
#pragma unroll
        for (int i = 0; i < 8; i++)
#pragma unroll
            for (int j = 0; j < 8; j++) acc[i][j] = fmaf(a[i], b[j], acc[i][j]);
    }

    float bb[8];
    *(float4*)(bb)     = *(const float4*)(g_bf + tn);
    *(float4*)(bb + 4) = *(const float4*)(g_bf + tn + 4);

    // per-row softmax across 8-lane segments (lanes t&~7 .. | 7 share rows)
#pragma unroll
    for (int i = 0; i < 8; i++) {
        float v[8];
        float mx = -1e30f;
#pragma unroll
        for (int j = 0; j < 8; j++) { v[j] = acc[i][j] + bb[j]; mx = fmaxf(mx, v[j]); }
        mx = fmaxf(mx, __shfl_xor_sync(0xffffffffu, mx, 1));
        mx = fmaxf(mx, __shfl_xor_sync(0xffffffffu, mx, 2));
        mx = fmaxf(mx, __shfl_xor_sync(0xffffffffu, mx, 4));
        float s = 0.f;
#pragma unroll
        for (int j = 0; j < 8; j++) { v[j] = __expf(v[j] - mx); s += v[j]; }
        s += __shfl_xor_sync(0xffffffffu, s, 1);
        s += __shfl_xor_sync(0xffffffffu, s, 2);
        s += __shfl_xor_sync(0xffffffffu, s, 4);
        float inv = __fdividef(1.0f, s);
#pragma unroll
        for (int j = 0; j < 8; j++) v[j] *= inv;
        size_t row = (size_t)(row0 + tm + i);
        float* pr = g_pack + row * 320;
        *(float4*)(pr + tn)     = *(float4*)(v);
        *(float4*)(pr + tn + 4) = *(float4*)(v + 4);
    }
}

// =====================================================================
// Kernel 3: sequential scan. One CTA per batch. Mv[64][128] in registers.
// =====================================================================
__device__ __forceinline__ void stage_store(float (*buf)[384], const float* v) {
    const int t = threadIdx.x;
#pragma unroll
    for (int k = 0; k < 5; k++) {
        int idx = t + 256 * k;           // 0..1279
        int q = idx / 320;
        int j = idx - q * 320;
        if (j < 64) { buf[q][2 * j] = v[k]; buf[q][2 * j + 1] = v[k]; }
        else        { buf[q][64 + j] = v[k]; }
    }
}

__global__ __launch_bounds__(256) void scan_kernel(const float* __restrict__ mv0,
                                                   float* __restrict__ rout) {
    __shared__ __align__(16) float sbuf[2][4][384];
    const int b  = blockIdx.x;
    const int t  = threadIdx.x;
    const int dp = t >> 2;
    const int mq = t & 3;
    const int m0 = mq * 16;

    unsigned long long Mv[16];
#pragma unroll
    for (int i = 0; i < 16; i++)
        Mv[i] = *(const unsigned long long*)(mv0 + (m0 + i) * 128 + 2 * dp);

    const float* pk = g_pack + (size_t)b * (SS * 320);
    float stg[5];
#pragma unroll
    for (int k = 0; k < 5; k++) stg[k] = pk[t + 256 * k];
    stage_store(sbuf[0], stg);
    __syncthreads();

    float* rb = rout + (size_t)b * (SS * 128) + 2 * dp;
    const int NCHUNK = SS / 4;

    for (int c = 0; c < NCHUNK; c++) {
        const int pb = c & 1;
        const bool more = (c + 1 < NCHUNK);
        if (more) {
            const float* pn = pk + (size_t)(c + 1) * 1280;
#pragma unroll
            for (int k = 0; k < 5; k++) stg[k] = pn[t + 256 * k];
        }
#pragma unroll
        for (int q = 0; q < 4; q++) {
            const float* bq = sbuf[pb][q];
            unsigned long long e2 = *(const unsigned long long*)(bq + 128 + 2 * dp);
            unsigned long long a2 = *(const unsigned long long*)(bq + 256 + 2 * dp);
            unsigned long long ne2 = e2 ^ 0x8000000080000000ULL;
            unsigned long long r2a = 0ULL, r2b = 0ULL;
#pragma unroll
            for (int i = 0; i < 16; i += 2) {
                ulonglong2 ww = *(const ulonglong2*)(bq + 2 * (m0 + i));
                r2a = f2fma(ww.x, Mv[i], r2a);                 // r += w*Mv (old Mv)
                unsigned long long t0 = f2fma(ne2, Mv[i], a2); // a - e*Mv
                Mv[i] = f2fma(ww.x, t0, Mv[i]);                // Mv += w*(a - e*Mv)
                r2b = f2fma(ww.y, Mv[i + 1], r2b);
                unsigned long long t1 = f2fma(ne2, Mv[i + 1], a2);
                Mv[i + 1] = f2fma(ww.y, t1, Mv[i + 1]);
            }
            unsigned long long r2 = f2add(r2a, r2b);
            float rx = __uint_as_float((unsigned)(r2 & 0xffffffffu));
            float ry = __uint_as_float((unsigned)(r2 >> 32));
            rx += __shfl_xor_sync(0xffffffffu, rx, 1);
            ry += __shfl_xor_sync(0xffffffffu, ry, 1);
            rx += __shfl_xor_sync(0xffffffffu, rx, 2);
            ry += __shfl_xor_sync(0xffffffffu, ry, 2);
            if (mq == 0) {
                float2 rv; rv.x = rx; rv.y = ry;
                *(float2*)(rb + (size_t)(c * 4 + q) * 128) = rv;
            }
        }
        if (more) stage_store(sbuf[pb ^ 1], stg);
        __syncthreads();
    }
}

// =====================================================================
// Kernel 4: y = sigmoid(r @ Wp + bp) -> out.  [131072,128]@[128,128].
// =====================================================================
__global__ __launch_bounds__(256, 2) void out_kernel(const float* __restrict__ Wp,
                                                     const float* __restrict__ bp,
                                                     float* __restrict__ out) {
    __shared__ __align__(16) float As[16][132];
    __shared__ __align__(16) float Bs[16][128];
    const int row0 = blockIdx.x * 128;
    const int t = threadIdx.x;
    const int tm = (t >> 4) * 8;
    const int tn = (t & 15) * 8;

    const int mA0 = t >> 2;
    const int kqA = (t & 3) * 4;
    const int kkB0 = t >> 5;
    const int nqB = (t & 31) * 4;

    const float* rA0p = g_r + (size_t)(row0 + mA0) * DD + kqA;
    const float* rA1p = g_r + (size_t)(row0 + mA0 + 64) * DD + kqA;
    const float* wB0 = Wp + (size_t)kkB0 * 128 + nqB;
    const float* wB1 = Wp + (size_t)(kkB0 + 8) * 128 + nqB;

    float acc[8][8];
#pragma unroll
    for (int i = 0; i < 8; i++)
#pragma unroll
        for (int j = 0; j < 8; j++) acc[i][j] = 0.f;

    float4 rA0, rA1, rB0, rB1;
    rA0 = *(const float4*)(rA0p);
    rA1 = *(const float4*)(rA1p);
    rB0 = *(const float4*)(wB0);
    rB1 = *(const float4*)(wB1);
    As[kqA + 0][mA0] = rA0.x; As[kqA + 1][mA0] = rA0.y;
    As[kqA + 2][mA0] = rA0.z; As[kqA + 3][mA0] = rA0.w;
    As[kqA + 0][mA0 + 64] = rA1.x; As[kqA + 1][mA0 + 64] = rA1.y;
    As[kqA + 2][mA0 + 64] = rA1.z; As[kqA + 3][mA0 + 64] = rA1.w;
    *(float4*)&Bs[kkB0][nqB] = rB0;
    *(float4*)&Bs[kkB0 + 8][nqB] = rB1;
    __syncthreads();

    for (int k0 = 16; k0 < DD; k0 += 16) {
        rA0 = *(const float4*)(rA0p + k0);
        rA1 = *(const float4*)(rA1p + k0);
        rB0 = *(const float4*)(wB0 + (size_t)k0 * 128);
        rB1 = *(const float4*)(wB1 + (size_t)k0 * 128);
#pragma unroll
        for (int kk = 0; kk < 16; kk++) {
            float a[8], b[8];
            *(float4*)(a)     = *(const float4*)&As[kk][tm];
            *(float4*)(a + 4) = *(const float4*)&As[kk][tm + 4];
            *(float4*)(b)     = *(const float4*)&Bs[kk][tn];
            *(float4*)(b + 4) = *(const float4*)&Bs[kk][tn + 4];
#pragma unroll
            for (int i = 0; i < 8; i++)
#pragma unroll
                for (int j = 0; j < 8; j++) acc[i][j] = fmaf(a[i], b[j], acc[i][j]);
        }
        __syncthreads();
        As[kqA + 0][mA0] = rA0.x; As[kqA + 1][mA0] = rA0.y;
        As[kqA + 2][mA0] = rA0.z; As[kqA + 3][mA0] = rA0.w;
        As[kqA + 0][mA0 + 64] = rA1.x; As[kqA + 1][mA0 + 64] = rA1.y;
        As[kqA + 2][mA0 + 64] = rA1.z; As[kqA + 3][mA0 + 64] = rA1.w;
        *(float4*)&Bs[kkB0][nqB] = rB0;
        *(float4*)&Bs[kkB0 + 8][nqB] = rB1;
        __syncthreads();
    }
#pragma unroll
    for (int kk = 0; kk < 16; kk++) {
        float a[8], b[8];
        *(float4*)(a)     = *(const float4*)&As[kk][tm];
        *(float4*)(a + 4) = *(const float4*)&As[kk][tm + 4];
        *(float4*)(b)     = *(const float4*)&Bs[kk][tn];
        *(float4*)(b + 4) = *(const float4*)&Bs[kk][tn + 4];
#pragma unroll
        for (int i = 0; i < 8; i++)
#pragma unroll
            for (int j = 0; j < 8; j++) acc[i][j] = fmaf(a[i], b[j], acc[i][j]);
    }

    float bb[8];
    *(float4*)(bb)     = *(const float4*)(bp + tn);
    *(float4*)(bb + 4) = *(const float4*)(bp + tn + 4);
#pragma unroll
    for (int i = 0; i < 8; i++) {
        size_t row = (size_t)(row0 + tm + i);
        float o[8];
#pragma unroll
        for (int j = 0; j < 8; j++) o[j] = fast_sigmoid(acc[i][j] + bb[j]);
        *(float4*)(out + row * OUTD + tn)     = *(float4*)(o);
        *(float4*)(out + row * OUTD + tn + 4) = *(float4*)(o + 4);
    }
}

// =====================================================================
// Launch
// =====================================================================
extern "C" void kernel_launch(void* const* d_in, const int* in_sizes, int n_in,
                              void* d_out, int out_size) {
    const float* x   = (const float*)d_in[0];
    const float* mk  = (const float*)d_in[1];
    const float* mv  = (const float*)d_in[2];
    const float* Wr  = (const float*)d_in[3];
    const float* br  = (const float*)d_in[4];
    const float* Ww  = (const float*)d_in[5];
    const float* bw  = (const float*)d_in[6];
    const float* Wp  = (const float*)d_in[7];
    const float* bp  = (const float*)d_in[8];
    float* out = (float*)d_out;

    float* gr;
    cudaGetSymbolAddress((void**)&gr, g_r);

    prep_kernel<<<64, 256>>>(Wr, br, mk);
    vproj_kernel<<<NROWS / 128, 256>>>(x, Ww, bw);
    wproj_kernel<<<NROWS / 256, 256>>>(x);
    scan_kernel<<<BB, 256>>>(mv, gr);
    out_kernel<<<NROWS / 128, 256>>>(Wp, bp, out);
}

// round 3
// speedup vs baseline: 2.2207x; 2.2207x over previous
#include <cuda_runtime.h>
#include <cuda_bf16.h>
#include <math.h>

// Problem constants
#define BB 128
#define SS 1024
#define IND 256
#define DD 128
#define MM 64
#define OUTD 128
#define NROWS (BB * SS)   // 131072

// Scratch (device globals). g_pack per (b,s): [0..64) w, [64..192) e, [192..320) a
__device__ float g_pack[(size_t)NROWS * 320];
__device__ float g_r[(size_t)NROWS * DD];
__device__ float g_wf[IND * MM];   // Wr @ MK^T  [256,64]
__device__ float g_bf[MM];         // br @ MK^T  [64]

// ---------------- f32x2 helpers ----------------
__device__ __forceinline__ unsigned long long f2fma(unsigned long long a,
                                                    unsigned long long b,
                                                    unsigned long long c) {
    unsigned long long d;
    asm("fma.rn.f32x2 %0, %1, %2, %3;" : "=l"(d) : "l"(a), "l"(b), "l"(c));
    return d;
}

// ---------------- fast activations ----------------
__device__ __forceinline__ float fast_sigmoid(float v) {
    float t = __expf(-v);
    return __fdividef(1.0f, 1.0f + t);
}
__device__ __forceinline__ float fast_tanh(float v) {
    float t = __expf(fminf(2.0f * v, 80.0f));
    return __fdividef(t - 1.0f, t + 1.0f);
}

// =====================================================================
// Kernel 0: prep.  g_wf = Wr @ MK^T, g_bf = br @ MK^T.   (tiny)
// =====================================================================
__global__ __launch_bounds__(256) void prep_kernel(const float* __restrict__ Wr,
                                                   const float* __restrict__ br,
                                                   const float* __restrict__ mk) {
    int gid = blockIdx.x * 256 + threadIdx.x;   // 0..16383
    int i = gid >> 6, m = gid & 63;
    float s = 0.f;
    const float* wr = Wr + i * 128;
    const float* mr = mk + m * 128;
#pragma unroll 4
    for (int d = 0; d < 128; d += 4) {
        float4 a = *(const float4*)(wr + d);
        float4 b = *(const float4*)(mr + d);
        s += a.x * b.x + a.y * b.y + a.z * b.z + a.w * b.w;
    }
    g_wf[i * 64 + m] = s;
    if (gid < 64) {
        float sb = 0.f;
        const float* mr2 = mk + gid * 128;
        for (int d = 0; d < 128; d++) sb += br[d] * mr2[d];
        g_bf[gid] = sb;
    }
}

// =====================================================================
// Kernel 1: v-projection (R1-style loop).  v = x@Ww + bw; e=sigmoid, a=tanh.
// 128x128 tile, K=256, BK=16, 8x8/thread.
// =====================================================================
__global__ __launch_bounds__(256) void vproj_kernel(
    const float* __restrict__ x,
    const float* __restrict__ Ww, const float* __restrict__ bw) {
    __shared__ __align__(16) float As[16][132];
    __shared__ __align__(16) float Bs[16][128];

    const int row0 = blockIdx.x * 128;
    const int t = threadIdx.x;
    const int tm = (t >> 4) * 8;
    const int tn = (t & 15) * 8;

    float acc[8][8];
#pragma unroll
    for (int i = 0; i < 8; i++)
#pragma unroll
        for (int j = 0; j < 8; j++) acc[i][j] = 0.f;

    for (int k0 = 0; k0 < IND; k0 += 16) {
#pragma unroll
        for (int i = 0; i < 2; i++) {
            int idx = t + i * 256;
            int m  = idx >> 2;
            int kq = (idx & 3) * 4;
            float4 v = *(const float4*)(x + (size_t)(row0 + m) * IND + k0 + kq);
            As[kq + 0][m] = v.x; As[kq + 1][m] = v.y;
            As[kq + 2][m] = v.z; As[kq + 3][m] = v.w;
        }
#pragma unroll
        for (int i = 0; i < 2; i++) {
            int idx = t + i * 256;
            int kk = idx >> 5;
            int nq = (idx & 31) * 4;
            *(float4*)&Bs[kk][nq] = *(const float4*)(Ww + (size_t)(k0 + kk) * 128 + nq);
        }
        __syncthreads();
#pragma unroll
        for (int kk = 0; kk < 16; kk++) {
            float a[8], b[8];
            *(float4*)(a)     = *(const float4*)&As[kk][tm];
            *(float4*)(a + 4) = *(const float4*)&As[kk][tm + 4];
            *(float4*)(b)     = *(const float4*)&Bs[kk][tn];
            *(float4*)(b + 4) = *(const float4*)&Bs[kk][tn + 4];
#pragma unroll
            for (int i = 0; i < 8; i++)
#pragma unroll
                for (int j = 0; j < 8; j++) acc[i][j] = fmaf(a[i], b[j], acc[i][j]);
        }
        __syncthreads();
    }

    float bb[8];
    *(float4*)(bb)     = *(const float4*)(bw + tn);
    *(float4*)(bb + 4) = *(const float4*)(bw + tn + 4);

#pragma unroll
    for (int i = 0; i < 8; i++) {
        size_t row = (size_t)(row0 + tm + i);
        float e[8], av[8];
#pragma unroll
        for (int j = 0; j < 8; j++) {
            float v = acc[i][j] + bb[j];
            e[j]  = fast_sigmoid(v);
            av[j] = fast_tanh(v);
        }
        float* pr = g_pack + row * 320;
        *(float4*)(pr + 64 + tn)      = *(float4*)(e);
        *(float4*)(pr + 64 + tn + 4)  = *(float4*)(e + 4);
        *(float4*)(pr + 192 + tn)     = *(float4*)(av);
        *(float4*)(pr + 192 + tn + 4) = *(float4*)(av + 4);
    }
}

// =====================================================================
// Kernel 2: w-projection + softmax (R1-style loop).
// w = softmax(x@Wf + bf) -> g_pack[.,0..64).  256x64 tile, 8x8/thread.
// =====================================================================
__global__ __launch_bounds__(256) void wproj_kernel(const float* __restrict__ x) {
    __shared__ __align__(16) float As[16][260];
    __shared__ __align__(16) float Bs[16][64];

    const int row0 = blockIdx.x * 256;
    const int t = threadIdx.x;
    const int tm = (t >> 3) * 8;          // 0..248
    const int tn = (t & 7) * 8;           // 0..56

    float acc[8][8];
#pragma unroll
    for (int i = 0; i < 8; i++)
#pragma unroll
        for (int j = 0; j < 8; j++) acc[i][j] = 0.f;

    for (int k0 = 0; k0 < IND; k0 += 16) {
        // A: 16k x 256m -> 4 float4 per thread
#pragma unroll
        for (int u = 0; u < 4; u++) {
            int idx = t + u * 256;        // 0..1023
            int m  = idx >> 2;            // 0..255
            int kq = (idx & 3) * 4;
            float4 v = *(const float4*)(x + (size_t)(row0 + m) * IND + k0 + kq);
            As[kq + 0][m] = v.x; As[kq + 1][m] = v.y;
            As[kq + 2][m] = v.z; As[kq + 3][m] = v.w;
        }
        // B: 16k x 64n -> 1 float4 per thread
        {
            int kk = t >> 4;
            int nq = (t & 15) * 4;
            *(float4*)&Bs[kk][nq] = *(const float4*)(g_wf + (size_t)(k0 + kk) * 64 + nq);
        }
        __syncthreads();
#pragma unroll
        for (int kk = 0; kk < 16; kk++) {
            float a[8], b[8];
            *(float4*)(a)     = *(const float4*)&As[kk][tm];
            *(float4*)(a + 4) = *(const float4*)&As[kk][tm + 4];
            *(float4*)(b)     = *(const float4*)&Bs[kk][tn];
            *(float4*)(b + 4) = *(const float4*)&Bs[kk][tn + 4];
#pragma unroll
            for (int i = 0; i < 8; i++)
#pragma unroll
                for (int j = 0; j < 8; j++) acc[i][j] = fmaf(a[i], b[j], acc[i][j]);
        }
        __syncthreads();
    }

    float bb[8];
    *(float4*)(bb)     = *(const float4*)(g_bf + tn);
    *(float4*)(bb + 4) = *(const float4*)(g_bf + tn + 4);

    // softmax across the 8-lane segment sharing a row
#pragma unroll
    for (int i = 0; i < 8; i++) {
        float v[8];
        float mx = -1e30f;
#pragma unroll
        for (int j = 0; j < 8; j++) { v[j] = acc[i][j] + bb[j]; mx = fmaxf(mx, v[j]); }
        mx = fmaxf(mx, __shfl_xor_sync(0xffffffffu, mx, 1));
        mx = fmaxf(mx, __shfl_xor_sync(0xffffffffu, mx, 2));
        mx = fmaxf(mx, __shfl_xor_sync(0xffffffffu, mx, 4));
        float s = 0.f;
#pragma unroll
        for (int j = 0; j < 8; j++) { v[j] = __expf(v[j] - mx); s += v[j]; }
        s += __shfl_xor_sync(0xffffffffu, s, 1);
        s += __shfl_xor_sync(0xffffffffu, s, 2);
        s += __shfl_xor_sync(0xffffffffu, s, 4);
        float inv = __fdividef(1.0f, s);
#pragma unroll
        for (int j = 0; j < 8; j++) v[j] *= inv;
        size_t row = (size_t)(row0 + tm + i);
        float* pr = g_pack + row * 320;
        *(float4*)(pr + tn)     = *(float4*)(v);
        *(float4*)(pr + tn + 4) = *(float4*)(v + 4);
    }
}

// =====================================================================
// Kernel 3: sequential scan, v2. 512 threads/CTA, one CTA per batch.
// Thread t: dp = t>>3 (d = 2dp,2dp+1), mq = t&7, m in [8*mq, 8*mq+8).
// Mv: 8 packed f32x2 registers.
// SMEM slot layout (384 floats): [0..128) w pairs TRANSPOSED
//   (pair for m at pair-index (m%8)*8 + m/8  -> conflict-free for mq lanes),
//   [128..256) e natural, [256..384) a natural.
// =====================================================================
__device__ __forceinline__ void stage_store2(float (*buf)[384], const float* v) {
    const int t = threadIdx.x;
#pragma unroll
    for (int k = 0; k < 3; k++) {
        int idx = t + 512 * k;           // 0..1535, valid < 1280
        if (idx < 1280) {
            int q = idx / 320;
            int j = idx - q * 320;
            if (j < 64) {
                int pi = (j & 7) * 8 + (j >> 3);   // transposed pair index
                buf[q][2 * pi]     = v[k];
                buf[q][2 * pi + 1] = v[k];
            } else {
                buf[q][64 + j] = v[k];             // e:[128..256), a:[256..384)
            }
        }
    }
}

__global__ __launch_bounds__(512) void scan_kernel(const float* __restrict__ mv0,
                                                   float* __restrict__ rout) {
    __shared__ __align__(16) float sbuf[2][4][384];
    const int b  = blockIdx.x;
    const int t  = threadIdx.x;
    const int dp = t >> 3;        // 0..63
    const int mq = t & 7;         // 0..7
    const int m0 = mq * 8;

    unsigned long long Mv[8];
#pragma unroll
    for (int i = 0; i < 8; i++)
        Mv[i] = *(const unsigned long long*)(mv0 + (m0 + i) * 128 + 2 * dp);

    const float* pk = g_pack + (size_t)b * (SS * 320);
    float stg[3];
#pragma unroll
    for (int k = 0; k < 3; k++) {
        int idx = t + 512 * k;
        stg[k] = (idx < 1280) ? pk[idx] : 0.f;
    }
    stage_store2(sbuf[0], stg);
    __syncthreads();

    float* rb = rout + (size_t)b * (SS * 128) + 2 * dp;
    const int NCHUNK = SS / 4;

    for (int c = 0; c < NCHUNK; c++) {
        const int pb = c & 1;
        const bool more = (c + 1 < NCHUNK);
        if (more) {
            const float* pn = pk + (size_t)(c + 1) * 1280;
#pragma unroll
            for (int k = 0; k < 3; k++) {
                int idx = t + 512 * k;
                if (idx < 1280) stg[k] = pn[idx];
            }
        }
#pragma unroll
        for (int q = 0; q < 4; q++) {
            const float* bq = sbuf[pb][q];
            unsigned long long e2 = *(const unsigned long long*)(bq + 128 + 2 * dp);
            unsigned long long a2 = *(const unsigned long long*)(bq + 256 + 2 * dp);
            unsigned long long ne2 = e2 ^ 0x8000000080000000ULL;
            unsigned long long r2a = 0ULL, r2b = 0ULL;
#pragma unroll
            for (int i = 0; i < 8; i += 2) {
                unsigned long long w0 = *(const unsigned long long*)(bq + 2 * ((i    ) * 8 + mq));
                unsigned long long w1 = *(const unsigned long long*)(bq + 2 * ((i + 1) * 8 + mq));
                r2a = f2fma(w0, Mv[i], r2a);
                unsigned long long t0 = f2fma(ne2, Mv[i], a2);
                Mv[i] = f2fma(w0, t0, Mv[i]);
                r2b = f2fma(w1, Mv[i + 1], r2b);
                unsigned long long t1 = f2fma(ne2, Mv[i + 1], a2);
                Mv[i + 1] = f2fma(w1, t1, Mv[i + 1]);
            }
            float rx = __uint_as_float((unsigned)(r2a & 0xffffffffu)) +
                       __uint_as_float((unsigned)(r2b & 0xffffffffu));
            float ry = __uint_as_float((unsigned)(r2a >> 32)) +
                       __uint_as_float((unsigned)(r2b >> 32));
            rx += __shfl_xor_sync(0xffffffffu, rx, 1);
            ry += __shfl_xor_sync(0xffffffffu, ry, 1);
            rx += __shfl_xor_sync(0xffffffffu, rx, 2);
            ry += __shfl_xor_sync(0xffffffffu, ry, 2);
            rx += __shfl_xor_sync(0xffffffffu, rx, 4);
            ry += __shfl_xor_sync(0xffffffffu, ry, 4);
            if (mq == 0) {
                float2 rv; rv.x = rx; rv.y = ry;
                *(float2*)(rb + (size_t)(c * 4 + q) * 128) = rv;
            }
        }
        if (more) stage_store2(sbuf[pb ^ 1], stg);
        __syncthreads();
    }
}

// =====================================================================
// Kernel 4: y = sigmoid(r @ Wp + bp) -> out (R1-style loop).
// =====================================================================
__global__ __launch_bounds__(256) void out_kernel(const float* __restrict__ Wp,
                                                  const float* __restrict__ bp,
                                                  float* __restrict__ out) {
    __shared__ __align__(16) float As[16][132];
    __shared__ __align__(16) float Bs[16][128];
    const int row0 = blockIdx.x * 128;
    const int t = threadIdx.x;
    const int tm = (t >> 4) * 8;
    const int tn = (t & 15) * 8;

    float acc[8][8];
#pragma unroll
    for (int i = 0; i < 8; i++)
#pragma unroll
        for (int j = 0; j < 8; j++) acc[i][j] = 0.f;

    for (int k0 = 0; k0 < DD; k0 += 16) {
#pragma unroll
        for (int i = 0; i < 2; i++) {
            int idx = t + i * 256;
            int m  = idx >> 2;
            int kq = (idx & 3) * 4;
            float4 v = *(const float4*)(g_r + (size_t)(row0 + m) * DD + k0 + kq);
            As[kq + 0][m] = v.x; As[kq + 1][m] = v.y;
            As[kq + 2][m] = v.z; As[kq + 3][m] = v.w;
        }
#pragma unroll
        for (int i = 0; i < 2; i++) {
            int idx = t + i * 256;
            int kk = idx >> 5;
            int nq = (idx & 31) * 4;
            *(float4*)&Bs[kk][nq] = *(const float4*)(Wp + (size_t)(k0 + kk) * 128 + nq);
        }
        __syncthreads();
#pragma unroll
        for (int kk = 0; kk < 16; kk++) {
            float a[8], b[8];
            *(float4*)(a)     = *(const float4*)&As[kk][tm];
            *(float4*)(a + 4) = *(const float4*)&As[kk][tm + 4];
            *(float4*)(b)     = *(const float4*)&Bs[kk][tn];
            *(float4*)(b + 4) = *(const float4*)&Bs[kk][tn + 4];
#pragma unroll
            for (int i = 0; i < 8; i++)
#pragma unroll
                for (int j = 0; j < 8; j++) acc[i][j] = fmaf(a[i], b[j], acc[i][j]);
        }
        __syncthreads();
    }

    float bb[8];
    *(float4*)(bb)     = *(const float4*)(bp + tn);
    *(float4*)(bb + 4) = *(const float4*)(bp + tn + 4);
#pragma unroll
    for (int i = 0; i < 8; i++) {
        size_t row = (size_t)(row0 + tm + i);
        float o[8];
#pragma unroll
        for (int j = 0; j < 8; j++) o[j] = fast_sigmoid(acc[i][j] + bb[j]);
        *(float4*)(out + row * OUTD + tn)     = *(float4*)(o);
        *(float4*)(out + row * OUTD + tn + 4) = *(float4*)(o + 4);
    }
}

// =====================================================================
// Launch
// =====================================================================
extern "C" void kernel_launch(void* const* d_in, const int* in_sizes, int n_in,
                              void* d_out, int out_size) {
    const float* x   = (const float*)d_in[0];
    const float* mk  = (const float*)d_in[1];
    const float* mv  = (const float*)d_in[2];
    const float* Wr  = (const float*)d_in[3];
    const float* br  = (const float*)d_in[4];
    const float* Ww  = (const float*)d_in[5];
    const float* bw  = (const float*)d_in[6];
    const float* Wp  = (const float*)d_in[7];
    const float* bp  = (const float*)d_in[8];
    float* out = (float*)d_out;

    float* gr;
    cudaGetSymbolAddress((void**)&gr, g_r);

    prep_kernel<<<64, 256>>>(Wr, br, mk);
    vproj_kernel<<<NROWS / 128, 256>>>(x, Ww, bw);
    wproj_kernel<<<NROWS / 256, 256>>>(x);
    scan_kernel<<<BB, 512>>>(mv, gr);
    out_kernel<<<NROWS / 128, 256>>>(Wp, bp, out);
}